// round 14
// baseline (speedup 1.0000x reference)
#include <cuda_runtime.h>
#include <cuda_bf16.h>
#include <math.h>
#include <float.h>

#define BATCH 4
#define SEQ   512
#define CDIM  768
#define NHEAD 12
#define HS    64
#define BH    (BATCH*NHEAD)      // 48
#define DW    8                  // warps (tokens) per dpp block

#define NX  (BATCH*SEQ*CDIM)     // 1572864
#define NWA (CDIM*3*CDIM)        // 1769472
#define NWP (CDIM*CDIM)          // 589824

// ---------------- device scratch (allocation forbidden) ----------------
__device__ float g_q   [BH*SEQ*HS];
__device__ float g_k   [BH*SEQ*HS];
__device__ float g_v   [BH*SEQ*HS];
__device__ float g_sim [(size_t)BH*SEQ*SEQ];   // q_i . k_j   (lower-tri blocks)
__device__ float g_gram[(size_t)BH*SEQ*SEQ];   // k_i . k_j   (lower-tri blocks)

// tf32 split operands (fp32 bit patterns)
__device__ float g_xh [NX],  g_xl [NX];
__device__ float g_Wah[NWA], g_Wal[NWA];
__device__ float g_Wph[NWP], g_Wpl[NWP];
__device__ float g_yh [NX],  g_yl [NX];     // written by dpp epilogue

// ---------------- helpers ----------------
__device__ __forceinline__ float tf32_rnd(float x)
{
    unsigned r;
    asm("cvt.rna.tf32.f32 %0, %1;" : "=r"(r) : "f"(x));
    return __uint_as_float(r);
}

__device__ __forceinline__ void mma_tf32(float* c, const float* a, float b0, float b1)
{
    asm volatile("mma.sync.aligned.m16n8k8.row.col.f32.tf32.tf32.f32 "
        "{%0,%1,%2,%3}, {%4,%5,%6,%7}, {%8,%9}, {%0,%1,%2,%3};"
        : "+f"(c[0]), "+f"(c[1]), "+f"(c[2]), "+f"(c[3])
        : "r"(__float_as_uint(a[0])), "r"(__float_as_uint(a[1])),
          "r"(__float_as_uint(a[2])), "r"(__float_as_uint(a[3])),
          "r"(__float_as_uint(b0)),   "r"(__float_as_uint(b1)));
}

__device__ __forceinline__ void cp16(unsigned dst, const float* src)
{
    asm volatile("cp.async.ca.shared.global [%0], [%1], 16;" :: "r"(dst), "l"(src));
}

// monotonic float<->u32 map: preserves total order, NaN maps above +inf
__device__ __forceinline__ unsigned fmap(float v)
{
    unsigned u = __float_as_uint(v);
    return (u & 0x80000000u) ? ~u : (u | 0x80000000u);
}
__device__ __forceinline__ float funmap(unsigned m)
{
    unsigned u = (m & 0x80000000u) ? (m ^ 0x80000000u) : ~m;
    return __uint_as_float(u);
}

// ---------------- fused split kernel: x, W_attn, W_proj -> tf32 hi/lo ------
__global__ __launch_bounds__(256)
void split3_kernel(const float* __restrict__ x, const float* __restrict__ wa,
                   const float* __restrict__ wp)
{
    int i = (blockIdx.x*256 + threadIdx.x) * 4;
    const float* s; float *hi, *lo; int off;
    if (i < NX)              { s = x;  hi = g_xh;  lo = g_xl;  off = i; }
    else if (i < NX+NWA)     { s = wa; hi = g_Wah; lo = g_Wal; off = i - NX; }
    else if (i < NX+NWA+NWP) { s = wp; hi = g_Wph; lo = g_Wpl; off = i - NX - NWA; }
    else return;
    float4 v = *(const float4*)(s + off);
    float4 h, l;
    h.x = tf32_rnd(v.x); l.x = tf32_rnd(v.x - h.x);
    h.y = tf32_rnd(v.y); l.y = tf32_rnd(v.y - h.y);
    h.z = tf32_rnd(v.z); l.z = tf32_rnd(v.z - h.z);
    h.w = tf32_rnd(v.w); l.w = tf32_rnd(v.w - h.w);
    *(float4*)&hi[off] = h;
    *(float4*)&lo[off] = l;
}

// ---------------- qkv scatter ----------------
__device__ __forceinline__ void scatter_qkv(int row, int gc, float v0, float v1)
{
    int sect = gc / CDIM;              // 0=q 1=k 2=v
    int cc = gc - sect*CDIM;
    int h = cc >> 6, dd = cc & 63;
    int bb = row >> 9, t = row & 511;
    size_t off = ((size_t)(bb*NHEAD + h)*SEQ + t)*HS + dd;
    float* dst = (sect == 0) ? g_q : (sect == 1 ? g_k : g_v);
    *(float2*)&dst[off] = make_float2(v0, v1);
}

// ---------------- 3xTF32 GEMM, cp.async 2-stage, K-chunk 16 ----------------
// MT = m-subtiles per warp (2 -> 128-row CTA, 1 -> 64-row CTA).
// Pass count is per-CTA: mode 0 (qkv): q/k columns 3 passes, v columns 1 pass.
//                        mode 1 (proj): 2 passes (output tolerance only).
template<int MT>
__global__ __launch_bounds__(256, 2)
void tf32_gemm(const float* __restrict__ bias, float* __restrict__ Cout,
               int M, int N, int K, int mode)
{
    constexpr int AROWS = 64*MT;
    constexpr int APART = AROWS*20;
    constexpr int BOFF  = 2*APART;
    constexpr int STGF  = BOFF + 2*2176;

    extern __shared__ __align__(16) float sm[];

    const float *Ah, *Al, *Bh, *Bl;
    if (mode == 0) { Ah = g_xh; Al = g_xl; Bh = g_Wah; Bl = g_Wal; }
    else           { Ah = g_yh; Al = g_yl; Bh = g_Wph; Bl = g_Wpl; }

    const int tid = threadIdx.x, lane = tid & 31, wid = tid >> 5;
    const int bm = blockIdx.y, bn = blockIdx.x;
    const int wm = wid & 3, wn = wid >> 2;
    const int g = lane >> 2, t = lane & 3;

    // per-CTA pass count: selection-critical q/k need 3; v + proj output-only
    const int passes = (mode == 0) ? ((bn >= 12) ? 1 : 3) : 2;

    const unsigned smbase = (unsigned)__cvta_generic_to_shared(sm);

    float acc[MT][8][4];
#pragma unroll
    for (int a = 0; a < MT; a++)
#pragma unroll
        for (int b = 0; b < 8; b++)
#pragma unroll
            for (int c = 0; c < 4; c++) acc[a][b][c] = 0.f;

    const int NC = K >> 4;

    auto issue = [&](int s, int k0) {
        unsigned base = smbase + (unsigned)(s*STGF)*4u;
        // A: 2 splits x AROWS rows x 4 quads -> 2*MT per thread
#pragma unroll
        for (int j = 0; j < 2*MT; j++) {
            int id = tid + 256*j;
            int sp = id / (256*MT), rem = id % (256*MT), row = rem >> 2, q = (rem & 3)*4;
            if (sp == 1 && passes < 3) continue;     // Al unused
            const float* src = (sp ? Al : Ah) + (size_t)(bm*AROWS + row)*K + k0 + q;
            cp16(base + (unsigned)(sp*APART + row*20 + q)*4u, src);
        }
        // B: 2 splits x 16 k-rows x 32 quads = 1024 -> 4/thread
#pragma unroll
        for (int j = 0; j < 4; j++) {
            int id = tid + 256*j;
            int sp = id >> 9, rem = id & 511, kr = rem >> 5, nq = (rem & 31)*4;
            if (sp == 1 && passes < 2) continue;     // Bl unused
            const float* src = (sp ? Bl : Bh) + (size_t)(k0 + kr)*N + bn*128 + nq;
            cp16(base + (unsigned)(BOFF + sp*2176 + kr*136 + nq)*4u, src);
        }
        asm volatile("cp.async.commit_group;");
    };

    issue(0, 0);

    for (int c = 0; c < NC; c++) {
        if (c + 1 < NC) {
            issue((c+1) & 1, (c+1)*16);
            asm volatile("cp.async.wait_group 1;");
        } else {
            asm volatile("cp.async.wait_group 0;");
        }
        __syncthreads();

        const float* S = sm + (c & 1)*STGF;

#pragma unroll
        for (int ks = 0; ks < 16; ks += 8) {
            float ah[MT][4], al[MT][4];
#pragma unroll
            for (int mt = 0; mt < MT; mt++) {
                int m0 = (wm*(16*MT) + mt*16 + g)*20 + ks + t;
                ah[mt][0] = S[m0];           ah[mt][1] = S[m0 + 160];
                ah[mt][2] = S[m0 + 4];       ah[mt][3] = S[m0 + 164];
                if (passes >= 3) {
                    al[mt][0] = S[APART + m0];   al[mt][1] = S[APART + m0 + 160];
                    al[mt][2] = S[APART + m0+4]; al[mt][3] = S[APART + m0 + 164];
                }
            }
            int nb0 = wn*64 + g;
            float bh0 = S[BOFF + (ks+t)*136 + nb0];
            float bh1 = S[BOFF + (ks+t+4)*136 + nb0];
            float bl0 = 0.f, bl1 = 0.f;
            if (passes >= 2) {
                bl0 = S[BOFF + 2176 + (ks+t)*136 + nb0];
                bl1 = S[BOFF + 2176 + (ks+t+4)*136 + nb0];
            }
#pragma unroll
            for (int nt = 0; nt < 8; nt++) {
                float cbh0 = bh0, cbh1 = bh1, cbl0 = bl0, cbl1 = bl1;
                if (nt < 7) {
                    int nb = wn*64 + (nt+1)*8 + g;
                    bh0 = S[BOFF + (ks+t)*136 + nb];
                    bh1 = S[BOFF + (ks+t+4)*136 + nb];
                    if (passes >= 2) {
                        bl0 = S[BOFF + 2176 + (ks+t)*136 + nb];
                        bl1 = S[BOFF + 2176 + (ks+t+4)*136 + nb];
                    }
                }
#pragma unroll
                for (int mt = 0; mt < MT; mt++) {
                    mma_tf32(acc[mt][nt], ah[mt], cbh0, cbh1);
                    if (passes >= 2) mma_tf32(acc[mt][nt], ah[mt], cbl0, cbl1);
                    if (passes >= 3) mma_tf32(acc[mt][nt], al[mt], cbh0, cbh1);
                }
            }
        }
        __syncthreads();
    }

    // epilogue
#pragma unroll
    for (int mt = 0; mt < MT; mt++) {
        int r0 = bm*AROWS + wm*(16*MT) + mt*16 + g;
#pragma unroll
        for (int nt = 0; nt < 8; nt++) {
            int gc = bn*128 + wn*64 + nt*8 + t*2;
            float b0 = bias[gc], b1 = bias[gc+1];
            float v00 = acc[mt][nt][0] + b0, v01 = acc[mt][nt][1] + b1;
            float v10 = acc[mt][nt][2] + b0, v11 = acc[mt][nt][3] + b1;
            if (mode == 1) {
                *(float2*)&Cout[(size_t)r0*N + gc]     = make_float2(v00, v01);
                *(float2*)&Cout[(size_t)(r0+8)*N + gc] = make_float2(v10, v11);
            } else {
                scatter_qkv(r0,     gc, v00, v01);
                scatter_qkv(r0 + 8, gc, v10, v11);
            }
        }
    }
}

#define STGF2 (2*2560 + 2*2176)
#define GEMM_SMEM2 (2*STGF2*4)          // MT=2 stage bytes
#define STGF1 (2*1280 + 2*2176)
#define GEMM_SMEM1 (2*STGF1*4)          // MT=1 stage bytes

// ---------------- sim+gram fused: Out = A K^T per head, 3xTF32, lower-tri --
#define APITCH 20
__global__ __launch_bounds__(256)
void sim_tf32()
{
    const int bm = blockIdx.y, bn = blockIdx.x;
    if (bn > bm) return;
    const int z = blockIdx.z;
    const int bh = (z < BH) ? z : (z - BH);
    const int mode = (z < BH) ? 0 : 1;

    __shared__ __align__(16) float Qs[2][128*APITCH];
    __shared__ __align__(16) float Ks[2][128*APITCH];

    const float* __restrict__ qb = (mode ? g_k : g_q) + (size_t)bh*SEQ*HS;
    const float* __restrict__ kb = g_k + (size_t)bh*SEQ*HS;

    const int tid = threadIdx.x, lane = tid & 31, wid = tid >> 5;
    const int wm = wid & 3, wn = wid >> 2;
    const int g = lane >> 2, t = lane & 3;

    float acc[2][8][4];
#pragma unroll
    for (int a = 0; a < 2; a++)
#pragma unroll
        for (int b = 0; b < 8; b++)
#pragma unroll
            for (int c = 0; c < 4; c++) acc[a][b][c] = 0.f;

    for (int d0 = 0; d0 < HS; d0 += 16) {
        if (d0 > 0) __syncthreads();
#pragma unroll
        for (int j = 0; j < 2; j++) {
            int id = tid*2 + j;
            int r = id >> 2, c = (id & 3)*4;
            float4 qv = *(const float4*)&qb[(size_t)(bm*128 + r)*HS + d0 + c];
            float4 kv = *(const float4*)&kb[(size_t)(bn*128 + r)*HS + d0 + c];
            float4 qh, ql, kh, kl;
            qh.x = tf32_rnd(qv.x); ql.x = tf32_rnd(qv.x - qh.x);
            qh.y = tf32_rnd(qv.y); ql.y = tf32_rnd(qv.y - qh.y);
            qh.z = tf32_rnd(qv.z); ql.z = tf32_rnd(qv.z - qh.z);
            qh.w = tf32_rnd(qv.w); ql.w = tf32_rnd(qv.w - qh.w);
            kh.x = tf32_rnd(kv.x); kl.x = tf32_rnd(kv.x - kh.x);
            kh.y = tf32_rnd(kv.y); kl.y = tf32_rnd(kv.y - kh.y);
            kh.z = tf32_rnd(kv.z); kl.z = tf32_rnd(kv.z - kh.z);
            kh.w = tf32_rnd(kv.w); kl.w = tf32_rnd(kv.w - kh.w);
            *(float4*)&Qs[0][r*APITCH + c] = qh;
            *(float4*)&Qs[1][r*APITCH + c] = ql;
            *(float4*)&Ks[0][r*APITCH + c] = kh;
            *(float4*)&Ks[1][r*APITCH + c] = kl;
        }
        __syncthreads();

#pragma unroll
        for (int ks = 0; ks < 16; ks += 8) {
            float ah[2][4], al[2][4];
#pragma unroll
            for (int mt = 0; mt < 2; mt++) {
                int m0 = (wm*32 + mt*16 + g)*APITCH + ks + t;
                int m1 = m0 + 8*APITCH;
                ah[mt][0] = Qs[0][m0];   ah[mt][1] = Qs[0][m1];
                ah[mt][2] = Qs[0][m0+4]; ah[mt][3] = Qs[0][m1+4];
                al[mt][0] = Qs[1][m0];   al[mt][1] = Qs[1][m1];
                al[mt][2] = Qs[1][m0+4]; al[mt][3] = Qs[1][m1+4];
            }
#pragma unroll
            for (int nt = 0; nt < 8; nt++) {
                int n0 = (wn*64 + nt*8 + g)*APITCH + ks + t;
                float bh0 = Ks[0][n0];
                float bh1 = Ks[0][n0+4];
                float bl0 = Ks[1][n0];
                float bl1 = Ks[1][n0+4];
#pragma unroll
                for (int mt = 0; mt < 2; mt++) {
                    mma_tf32(acc[mt][nt], ah[mt], bh0, bh1);
                    mma_tf32(acc[mt][nt], ah[mt], bl0, bl1);
                    mma_tf32(acc[mt][nt], al[mt], bh0, bh1);
                }
            }
        }
    }

    float* S = (mode ? g_gram : g_sim) + (size_t)bh*SEQ*SEQ;
#pragma unroll
    for (int mt = 0; mt < 2; mt++) {
        int r0 = bm*128 + wm*32 + mt*16 + g;
#pragma unroll
        for (int nt = 0; nt < 8; nt++) {
            int gc = bn*128 + wn*64 + nt*8 + t*2;
            *(float2*)&S[(size_t)r0*SEQ + gc]     = make_float2(acc[mt][nt][0], acc[mt][nt][1]);
            *(float2*)&S[(size_t)(r0+8)*SEQ + gc] = make_float2(acc[mt][nt][2], acc[mt][nt][3]);
        }
    }
}

// ---------------- DPP: gram gathered from g_gram (proven) -----------------
__global__ __launch_bounds__(32*DW)
void dpp_kernel()
{
    __shared__ float Gm[DW][17][17];

    const unsigned FULL = 0xffffffffu;
    const int lane = threadIdx.x & 31;
    const int wrp  = threadIdx.x >> 5;
    const int i  = blockIdx.x * DW + wrp;
    const int bh = blockIdx.y;
    const int nvalid = i + 1;

    const float* __restrict__ vb = g_v + (size_t)bh*SEQ*HS;
    const float* __restrict__ simRow = g_sim + ((size_t)bh*SEQ + i)*SEQ;
    const float* __restrict__ Gh = g_gram + (size_t)bh*SEQ*SEQ;

    float val[16];
    {
        const float4* sr = (const float4*)simRow;
#pragma unroll
        for (int q = 0; q < 4; q++) {
            float4 v4 = sr[lane*4 + q];
            val[q*4+0] = v4.x; val[q*4+1] = v4.y;
            val[q*4+2] = v4.z; val[q*4+3] = v4.w;
        }
    }
    int cnt = nvalid - lane*16;
    cnt = (cnt < 0) ? 0 : (cnt > 16 ? 16 : cnt);
    unsigned dead = (0xFFFFu << cnt) & 0xFFFFu;

    float bv1 = -INFINITY, bv2 = -INFINITY; int bc1 = 0, bc2 = 0;
#pragma unroll
    for (int c = 0; c < 16; c++) {
        float v = ((dead >> c) & 1u) ? -INFINITY : val[c];
        if (v > bv1)      { bv2 = bv1; bc2 = bc1; bv1 = v; bc1 = c; }
        else if (v > bv2) { bv2 = v; bc2 = c; }
    }
    bool have2 = true;

    float myVal = -INFINITY; int myIdx = i;
    for (int t = 0; t < 16; t++) {
        unsigned m = fmap(bv1);
        unsigned mmax = __reduce_max_sync(FULL, m);
        unsigned ball = __ballot_sync(FULL, m == mmax);
        int wl = __ffs(ball) - 1;
        int wc = __shfl_sync(FULL, bc1, wl);
        if (lane == t) { myVal = funmap(mmax); myIdx = wl*16 + wc; }
        if (lane == wl) {
            dead |= 1u << bc1;
            if (have2) {
                bv1 = bv2; bc1 = bc2; have2 = false;
            } else {
                bv1 = -INFINITY; bc1 = 0; bv2 = -INFINITY; bc2 = 0;
#pragma unroll
                for (int c = 0; c < 16; c++) {
                    float v = ((dead >> c) & 1u) ? -INFINITY : val[c];
                    if (v > bv1)      { bv2 = bv1; bc2 = bc1; bv1 = v; bc1 = c; }
                    else if (v > bv2) { bv2 = v; bc2 = c; }
                }
                have2 = true;
            }
        }
    }
    bool availb = (lane < 16) && (myVal > -INFINITY) && (myIdx != i);
    unsigned avail = __ballot_sync(FULL, availb) & 0xFFFFu;
    int safeIdx = (lane < 16 && myVal > -INFINITY) ? myIdx : i;

#pragma unroll
    for (int t2 = 0; t2 < 10; t2++) {
        int e = lane + 32*t2;
        int a = e / 17, b = e - a*17;
        int ta = __shfl_sync(FULL, safeIdx, a & 15);
        int tb = __shfl_sync(FULL, safeIdx, b & 15);
        if (e < 289) {
            int t_a = (a >= 16) ? i : ta;
            int t_b = (b >= 16) ? i : tb;
            int row = max(t_a, t_b), col = min(t_a, t_b);
            Gm[wrp][a][b] = Gh[(size_t)row*SEQ + col];
        }
    }
    __syncwarp();

    const int cl = lane & 15;
    float Gii  = Gm[wrp][16][16];
    float detS = Gii;
    float curS = -logf(Gii + 1e-6f);
    int count = 1;
    float w[8];
    float w0 = Gm[wrp][cl][16] / sqrtf(Gii);
    w[0] = w0;
#pragma unroll
    for (int j = 1; j < 8; j++) w[j] = 0.f;
    float ec = Gm[wrp][cl][cl] - w0*w0;
    int selTok[8];
#pragma unroll
    for (int j = 0; j < 8; j++) selTok[j] = i;

    for (int step = 0; step < 7; step++) {
        bool av = (lane < 16) && ((avail >> lane) & 1u);
        float s = av ? (-logf(detS*ec + 1e-6f) / (float)(count + 1)) : -INFINITY;
        unsigned m = fmap(s);
        unsigned mmax = __reduce_max_sync(FULL, m);
        unsigned ball = __ballot_sync(FULL, m == mmax);
        int bl = __ffs(ball) - 1;
        float bs = funmap(mmax);

        bool anyAvail = (avail != 0u);
        bool accept = anyAvail && ((bs > curS) || (count < 2));
        if (!accept) break;

        float eb = __shfl_sync(FULL, ec, bl);
        float Lb = sqrtf(eb);
        float dot = 0.f;
#pragma unroll
        for (int j = 0; j < 7; j++) {
            float wbj = __shfl_sync(FULL, w[j], bl);
            if (j < count) dot += w[j]*wbj;
        }
        float wn = (Gm[wrp][cl][bl] - dot) / Lb;
#pragma unroll
        for (int j = 1; j < 8; j++) if (j == count) w[j] = wn;
        ec -= wn*wn;
        detS *= eb;
        curS = bs;
        int btok = __shfl_sync(FULL, myIdx, bl);
#pragma unroll
        for (int j = 1; j < 8; j++) if (j == count) selTok[j] = btok;
        count++;
        avail &= ~(1u << bl);
    }

    float a0 = 0.f, a1 = 0.f;
#pragma unroll
    for (int r = 0; r < 8; r++) {
        if (r < count) {
            const float* vr = vb + (size_t)selTok[r]*HS;
            a0 += vr[lane];
            a1 += vr[lane + 32];
        }
    }
    float cnt2 = (float)count;
    float o0 = a0 / cnt2, o1 = a1 / cnt2;
    int bb = bh / NHEAD, h = bh % NHEAD;
    size_t yoff = ((size_t)(bb*SEQ + i))*CDIM + h*HS;
    float h0 = tf32_rnd(o0), l0 = tf32_rnd(o0 - h0);
    float h1 = tf32_rnd(o1), l1 = tf32_rnd(o1 - h1);
    g_yh[yoff + lane]      = h0;  g_yl[yoff + lane]      = l0;
    g_yh[yoff + lane + 32] = h1;  g_yl[yoff + lane + 32] = l1;
}

// ---------------------------------------------------------------------------
extern "C" void kernel_launch(void* const* d_in, const int* in_sizes, int n_in,
                              void* d_out, int out_size)
{
    const float* x      = (const float*)d_in[0];
    const float* W_attn = (const float*)d_in[1];
    const float* b_attn = (const float*)d_in[2];
    const float* W_proj = (const float*)d_in[3];
    const float* b_proj = (const float*)d_in[4];
    float* out = (float*)d_out;

    static int smem_set = 0;
    if (!smem_set) {
        cudaFuncSetAttribute(tf32_gemm<2>,
                             cudaFuncAttributeMaxDynamicSharedMemorySize,
                             GEMM_SMEM2);
        cudaFuncSetAttribute(tf32_gemm<1>,
                             cudaFuncAttributeMaxDynamicSharedMemorySize,
                             GEMM_SMEM1);
        smem_set = 1;
    }

    const int ntot = NX + NWA + NWP;
    split3_kernel<<<(ntot/4 + 255)/256, 256>>>(x, W_attn, W_proj);

    {   // QKV: q/k columns 3-pass, v columns 1-pass
        dim3 grid(3*CDIM/128, (BATCH*SEQ)/128);
        tf32_gemm<2><<<grid, 256, GEMM_SMEM2>>>(b_attn, out, BATCH*SEQ, 3*CDIM, CDIM, 0);
    }
    {   // sim + gram fused (lower-tri blocks, per head)
        dim3 grid(4, 4, 2*BH);
        sim_tf32<<<grid, 256>>>();
    }
    {   // DPP attention -> g_yh/g_yl
        dim3 grid(SEQ/DW, BH);
        dpp_kernel<<<grid, 32*DW>>>();
    }
    {   // Proj: 2-pass, 64-row tiles for full-chip spread
        dim3 grid(CDIM/128, (BATCH*SEQ)/64);
        tf32_gemm<1><<<grid, 256, GEMM_SMEM1>>>(b_proj, out, BATCH*SEQ, CDIM, CDIM, 1);
    }
}

// round 15
// speedup vs baseline: 1.0320x; 1.0320x over previous
#include <cuda_runtime.h>
#include <cuda_bf16.h>
#include <math.h>
#include <float.h>

#define BATCH 4
#define SEQ   512
#define CDIM  768
#define NHEAD 12
#define HS    64
#define BH    (BATCH*NHEAD)      // 48
#define DW    8                  // warps (tokens) per dpp block

#define NX  (BATCH*SEQ*CDIM)     // 1572864
#define NWA (CDIM*3*CDIM)        // 1769472
#define NWP (CDIM*CDIM)          // 589824

// ---------------- device scratch (allocation forbidden) ----------------
__device__ float g_q   [BH*SEQ*HS];
__device__ float g_k   [BH*SEQ*HS];
__device__ float g_v   [BH*SEQ*HS];
__device__ float g_sim [(size_t)BH*SEQ*SEQ];   // q_i . k_j   (lower-tri blocks)
__device__ float g_gram[(size_t)BH*SEQ*SEQ];   // k_i . k_j   (lower-tri blocks)

// tf32 split operands (fp32 bit patterns)
__device__ float g_xh [NX],  g_xl [NX];
__device__ float g_Wah[NWA], g_Wal[NWA];
__device__ float g_Wph[NWP], g_Wpl[NWP];
__device__ float g_yh [NX],  g_yl [NX];     // written by dpp epilogue

// ---------------- helpers ----------------
__device__ __forceinline__ float tf32_rnd(float x)
{
    unsigned r;
    asm("cvt.rna.tf32.f32 %0, %1;" : "=r"(r) : "f"(x));
    return __uint_as_float(r);
}

__device__ __forceinline__ void mma_tf32(float* c, const float* a, float b0, float b1)
{
    asm volatile("mma.sync.aligned.m16n8k8.row.col.f32.tf32.tf32.f32 "
        "{%0,%1,%2,%3}, {%4,%5,%6,%7}, {%8,%9}, {%0,%1,%2,%3};"
        : "+f"(c[0]), "+f"(c[1]), "+f"(c[2]), "+f"(c[3])
        : "r"(__float_as_uint(a[0])), "r"(__float_as_uint(a[1])),
          "r"(__float_as_uint(a[2])), "r"(__float_as_uint(a[3])),
          "r"(__float_as_uint(b0)),   "r"(__float_as_uint(b1)));
}

__device__ __forceinline__ void cp16(unsigned dst, const float* src)
{
    asm volatile("cp.async.ca.shared.global [%0], [%1], 16;" :: "r"(dst), "l"(src));
}

// monotonic float<->u32 map: preserves total order, NaN maps above +inf
__device__ __forceinline__ unsigned fmap(float v)
{
    unsigned u = __float_as_uint(v);
    return (u & 0x80000000u) ? ~u : (u | 0x80000000u);
}
__device__ __forceinline__ float funmap(unsigned m)
{
    unsigned u = (m & 0x80000000u) ? (m ^ 0x80000000u) : ~m;
    return __uint_as_float(u);
}

// ---------------- fused split kernel: x, W_attn, W_proj -> tf32 hi/lo ------
__global__ __launch_bounds__(256)
void split3_kernel(const float* __restrict__ x, const float* __restrict__ wa,
                   const float* __restrict__ wp)
{
    int i = (blockIdx.x*256 + threadIdx.x) * 4;
    const float* s; float *hi, *lo; int off;
    if (i < NX)              { s = x;  hi = g_xh;  lo = g_xl;  off = i; }
    else if (i < NX+NWA)     { s = wa; hi = g_Wah; lo = g_Wal; off = i - NX; }
    else if (i < NX+NWA+NWP) { s = wp; hi = g_Wph; lo = g_Wpl; off = i - NX - NWA; }
    else return;
    float4 v = *(const float4*)(s + off);
    float4 h, l;
    h.x = tf32_rnd(v.x); l.x = tf32_rnd(v.x - h.x);
    h.y = tf32_rnd(v.y); l.y = tf32_rnd(v.y - h.y);
    h.z = tf32_rnd(v.z); l.z = tf32_rnd(v.z - h.z);
    h.w = tf32_rnd(v.w); l.w = tf32_rnd(v.w - h.w);
    *(float4*)&hi[off] = h;
    *(float4*)&lo[off] = l;
}

// ---------------- qkv scatter ----------------
__device__ __forceinline__ void scatter_qkv(int row, int gc, float v0, float v1)
{
    int sect = gc / CDIM;              // 0=q 1=k 2=v
    int cc = gc - sect*CDIM;
    int h = cc >> 6, dd = cc & 63;
    int bb = row >> 9, t = row & 511;
    size_t off = ((size_t)(bb*NHEAD + h)*SEQ + t)*HS + dd;
    float* dst = (sect == 0) ? g_q : (sect == 1 ? g_k : g_v);
    *(float2*)&dst[off] = make_float2(v0, v1);
}

// ---------------- 3xTF32 GEMM, cp.async 2-stage, K-chunk 16 ----------------
// MT = m-subtiles per warp (2 -> 128-row CTA, 1 -> 64-row CTA).
// PASSES (compile-time): 3 = AhBh+AhBl+AlBh, 2 = AhBh+AhBl, 1 = AhBh.
// bn_off shifts the 128-column block index (for split qk / v launches).
template<int MT, int PASSES>
__global__ __launch_bounds__(256, 2)
void tf32_gemm(const float* __restrict__ bias, float* __restrict__ Cout,
               int M, int N, int K, int mode, int bn_off)
{
    constexpr int AROWS = 64*MT;
    constexpr int APART = AROWS*20;
    constexpr int BOFF  = 2*APART;
    constexpr int STGF  = BOFF + 2*2176;
    constexpr int AJ    = (PASSES >= 3) ? 2*MT : MT;   // A-copy iterations
    constexpr int BJ    = (PASSES >= 2) ? 4 : 2;       // B-copy iterations

    extern __shared__ __align__(16) float sm[];

    const float *Ah, *Al, *Bh, *Bl;
    if (mode == 0) { Ah = g_xh; Al = g_xl; Bh = g_Wah; Bl = g_Wal; }
    else           { Ah = g_yh; Al = g_yl; Bh = g_Wph; Bl = g_Wpl; }

    const int tid = threadIdx.x, lane = tid & 31, wid = tid >> 5;
    const int bm = blockIdx.y, bn = blockIdx.x + bn_off;
    const int wm = wid & 3, wn = wid >> 2;
    const int g = lane >> 2, t = lane & 3;

    const unsigned smbase = (unsigned)__cvta_generic_to_shared(sm);

    float acc[MT][8][4];
#pragma unroll
    for (int a = 0; a < MT; a++)
#pragma unroll
        for (int b = 0; b < 8; b++)
#pragma unroll
            for (int c = 0; c < 4; c++) acc[a][b][c] = 0.f;

    const int NC = K >> 4;

    auto issue = [&](int s, int k0) {
        unsigned base = smbase + (unsigned)(s*STGF)*4u;
#pragma unroll
        for (int j = 0; j < AJ; j++) {
            int id = tid + 256*j;
            int sp = id / (256*MT), rem = id % (256*MT), row = rem >> 2, q = (rem & 3)*4;
            const float* src = (sp ? Al : Ah) + (size_t)(bm*AROWS + row)*K + k0 + q;
            cp16(base + (unsigned)(sp*APART + row*20 + q)*4u, src);
        }
#pragma unroll
        for (int j = 0; j < BJ; j++) {
            int id = tid + 256*j;
            int sp = id >> 9, rem = id & 511, kr = rem >> 5, nq = (rem & 31)*4;
            const float* src = (sp ? Bl : Bh) + (size_t)(k0 + kr)*N + bn*128 + nq;
            cp16(base + (unsigned)(BOFF + sp*2176 + kr*136 + nq)*4u, src);
        }
        asm volatile("cp.async.commit_group;");
    };

    issue(0, 0);

    for (int c = 0; c < NC; c++) {
        if (c + 1 < NC) {
            issue((c+1) & 1, (c+1)*16);
            asm volatile("cp.async.wait_group 1;");
        } else {
            asm volatile("cp.async.wait_group 0;");
        }
        __syncthreads();

        const float* S = sm + (c & 1)*STGF;

#pragma unroll
        for (int ks = 0; ks < 16; ks += 8) {
            float ah[MT][4], al[MT][4];
#pragma unroll
            for (int mt = 0; mt < MT; mt++) {
                int m0 = (wm*(16*MT) + mt*16 + g)*20 + ks + t;
                ah[mt][0] = S[m0];           ah[mt][1] = S[m0 + 160];
                ah[mt][2] = S[m0 + 4];       ah[mt][3] = S[m0 + 164];
                if (PASSES >= 3) {
                    al[mt][0] = S[APART + m0];   al[mt][1] = S[APART + m0 + 160];
                    al[mt][2] = S[APART + m0+4]; al[mt][3] = S[APART + m0 + 164];
                }
            }
            int nb0 = wn*64 + g;
            float bh0 = S[BOFF + (ks+t)*136 + nb0];
            float bh1 = S[BOFF + (ks+t+4)*136 + nb0];
            float bl0 = 0.f, bl1 = 0.f;
            if (PASSES >= 2) {
                bl0 = S[BOFF + 2176 + (ks+t)*136 + nb0];
                bl1 = S[BOFF + 2176 + (ks+t+4)*136 + nb0];
            }
#pragma unroll
            for (int nt = 0; nt < 8; nt++) {
                float cbh0 = bh0, cbh1 = bh1, cbl0 = bl0, cbl1 = bl1;
                if (nt < 7) {
                    int nb = wn*64 + (nt+1)*8 + g;
                    bh0 = S[BOFF + (ks+t)*136 + nb];
                    bh1 = S[BOFF + (ks+t+4)*136 + nb];
                    if (PASSES >= 2) {
                        bl0 = S[BOFF + 2176 + (ks+t)*136 + nb];
                        bl1 = S[BOFF + 2176 + (ks+t+4)*136 + nb];
                    }
                }
#pragma unroll
                for (int mt = 0; mt < MT; mt++) {
                    mma_tf32(acc[mt][nt], ah[mt], cbh0, cbh1);
                    if (PASSES >= 2) mma_tf32(acc[mt][nt], ah[mt], cbl0, cbl1);
                    if (PASSES >= 3) mma_tf32(acc[mt][nt], al[mt], cbh0, cbh1);
                }
            }
        }
        __syncthreads();
    }

    // epilogue
#pragma unroll
    for (int mt = 0; mt < MT; mt++) {
        int r0 = bm*AROWS + wm*(16*MT) + mt*16 + g;
#pragma unroll
        for (int nt = 0; nt < 8; nt++) {
            int gc = bn*128 + wn*64 + nt*8 + t*2;
            float b0 = bias[gc], b1 = bias[gc+1];
            float v00 = acc[mt][nt][0] + b0, v01 = acc[mt][nt][1] + b1;
            float v10 = acc[mt][nt][2] + b0, v11 = acc[mt][nt][3] + b1;
            if (mode == 1) {
                *(float2*)&Cout[(size_t)r0*N + gc]     = make_float2(v00, v01);
                *(float2*)&Cout[(size_t)(r0+8)*N + gc] = make_float2(v10, v11);
            } else {
                scatter_qkv(r0,     gc, v00, v01);
                scatter_qkv(r0 + 8, gc, v10, v11);
            }
        }
    }
}

#define STGF2 (2*2560 + 2*2176)
#define GEMM_SMEM2 (2*STGF2*4)          // MT=2 stage bytes
#define STGF1 (2*1280 + 2*2176)
#define GEMM_SMEM1 (2*STGF1*4)          // MT=1 stage bytes

// ---------------- sim+gram fused: Out = A K^T per head, 3xTF32, lower-tri --
#define APITCH 20
__global__ __launch_bounds__(256)
void sim_tf32()
{
    const int bm = blockIdx.y, bn = blockIdx.x;
    if (bn > bm) return;
    const int z = blockIdx.z;
    const int bh = (z < BH) ? z : (z - BH);
    const int mode = (z < BH) ? 0 : 1;

    __shared__ __align__(16) float Qs[2][128*APITCH];
    __shared__ __align__(16) float Ks[2][128*APITCH];

    const float* __restrict__ qb = (mode ? g_k : g_q) + (size_t)bh*SEQ*HS;
    const float* __restrict__ kb = g_k + (size_t)bh*SEQ*HS;

    const int tid = threadIdx.x, lane = tid & 31, wid = tid >> 5;
    const int wm = wid & 3, wn = wid >> 2;
    const int g = lane >> 2, t = lane & 3;

    float acc[2][8][4];
#pragma unroll
    for (int a = 0; a < 2; a++)
#pragma unroll
        for (int b = 0; b < 8; b++)
#pragma unroll
            for (int c = 0; c < 4; c++) acc[a][b][c] = 0.f;

    for (int d0 = 0; d0 < HS; d0 += 16) {
        if (d0 > 0) __syncthreads();
#pragma unroll
        for (int j = 0; j < 2; j++) {
            int id = tid*2 + j;
            int r = id >> 2, c = (id & 3)*4;
            float4 qv = *(const float4*)&qb[(size_t)(bm*128 + r)*HS + d0 + c];
            float4 kv = *(const float4*)&kb[(size_t)(bn*128 + r)*HS + d0 + c];
            float4 qh, ql, kh, kl;
            qh.x = tf32_rnd(qv.x); ql.x = tf32_rnd(qv.x - qh.x);
            qh.y = tf32_rnd(qv.y); ql.y = tf32_rnd(qv.y - qh.y);
            qh.z = tf32_rnd(qv.z); ql.z = tf32_rnd(qv.z - qh.z);
            qh.w = tf32_rnd(qv.w); ql.w = tf32_rnd(qv.w - qh.w);
            kh.x = tf32_rnd(kv.x); kl.x = tf32_rnd(kv.x - kh.x);
            kh.y = tf32_rnd(kv.y); kl.y = tf32_rnd(kv.y - kh.y);
            kh.z = tf32_rnd(kv.z); kl.z = tf32_rnd(kv.z - kh.z);
            kh.w = tf32_rnd(kv.w); kl.w = tf32_rnd(kv.w - kh.w);
            *(float4*)&Qs[0][r*APITCH + c] = qh;
            *(float4*)&Qs[1][r*APITCH + c] = ql;
            *(float4*)&Ks[0][r*APITCH + c] = kh;
            *(float4*)&Ks[1][r*APITCH + c] = kl;
        }
        __syncthreads();

#pragma unroll
        for (int ks = 0; ks < 16; ks += 8) {
            float ah[2][4], al[2][4];
#pragma unroll
            for (int mt = 0; mt < 2; mt++) {
                int m0 = (wm*32 + mt*16 + g)*APITCH + ks + t;
                int m1 = m0 + 8*APITCH;
                ah[mt][0] = Qs[0][m0];   ah[mt][1] = Qs[0][m1];
                ah[mt][2] = Qs[0][m0+4]; ah[mt][3] = Qs[0][m1+4];
                al[mt][0] = Qs[1][m0];   al[mt][1] = Qs[1][m1];
                al[mt][2] = Qs[1][m0+4]; al[mt][3] = Qs[1][m1+4];
            }
#pragma unroll
            for (int nt = 0; nt < 8; nt++) {
                int n0 = (wn*64 + nt*8 + g)*APITCH + ks + t;
                float bh0 = Ks[0][n0];
                float bh1 = Ks[0][n0+4];
                float bl0 = Ks[1][n0];
                float bl1 = Ks[1][n0+4];
#pragma unroll
                for (int mt = 0; mt < 2; mt++) {
                    mma_tf32(acc[mt][nt], ah[mt], bh0, bh1);
                    mma_tf32(acc[mt][nt], ah[mt], bl0, bl1);
                    mma_tf32(acc[mt][nt], al[mt], bh0, bh1);
                }
            }
        }
    }

    float* S = (mode ? g_gram : g_sim) + (size_t)bh*SEQ*SEQ;
#pragma unroll
    for (int mt = 0; mt < 2; mt++) {
        int r0 = bm*128 + wm*32 + mt*16 + g;
#pragma unroll
        for (int nt = 0; nt < 8; nt++) {
            int gc = bn*128 + wn*64 + nt*8 + t*2;
            *(float2*)&S[(size_t)r0*SEQ + gc]     = make_float2(acc[mt][nt][0], acc[mt][nt][1]);
            *(float2*)&S[(size_t)(r0+8)*SEQ + gc] = make_float2(acc[mt][nt][2], acc[mt][nt][3]);
        }
    }
}

// ---------------- DPP: gram gathered from g_gram (proven) -----------------
__global__ __launch_bounds__(32*DW)
void dpp_kernel()
{
    __shared__ float Gm[DW][17][17];

    const unsigned FULL = 0xffffffffu;
    const int lane = threadIdx.x & 31;
    const int wrp  = threadIdx.x >> 5;
    const int i  = blockIdx.x * DW + wrp;
    const int bh = blockIdx.y;
    const int nvalid = i + 1;

    const float* __restrict__ vb = g_v + (size_t)bh*SEQ*HS;
    const float* __restrict__ simRow = g_sim + ((size_t)bh*SEQ + i)*SEQ;
    const float* __restrict__ Gh = g_gram + (size_t)bh*SEQ*SEQ;

    float val[16];
    {
        const float4* sr = (const float4*)simRow;
#pragma unroll
        for (int q = 0; q < 4; q++) {
            float4 v4 = sr[lane*4 + q];
            val[q*4+0] = v4.x; val[q*4+1] = v4.y;
            val[q*4+2] = v4.z; val[q*4+3] = v4.w;
        }
    }
    int cnt = nvalid - lane*16;
    cnt = (cnt < 0) ? 0 : (cnt > 16 ? 16 : cnt);
    unsigned dead = (0xFFFFu << cnt) & 0xFFFFu;

    float bv1 = -INFINITY, bv2 = -INFINITY; int bc1 = 0, bc2 = 0;
#pragma unroll
    for (int c = 0; c < 16; c++) {
        float v = ((dead >> c) & 1u) ? -INFINITY : val[c];
        if (v > bv1)      { bv2 = bv1; bc2 = bc1; bv1 = v; bc1 = c; }
        else if (v > bv2) { bv2 = v; bc2 = c; }
    }
    bool have2 = true;

    float myVal = -INFINITY; int myIdx = i;
    for (int t = 0; t < 16; t++) {
        unsigned m = fmap(bv1);
        unsigned mmax = __reduce_max_sync(FULL, m);
        unsigned ball = __ballot_sync(FULL, m == mmax);
        int wl = __ffs(ball) - 1;
        int wc = __shfl_sync(FULL, bc1, wl);
        if (lane == t) { myVal = funmap(mmax); myIdx = wl*16 + wc; }
        if (lane == wl) {
            dead |= 1u << bc1;
            if (have2) {
                bv1 = bv2; bc1 = bc2; have2 = false;
            } else {
                bv1 = -INFINITY; bc1 = 0; bv2 = -INFINITY; bc2 = 0;
#pragma unroll
                for (int c = 0; c < 16; c++) {
                    float v = ((dead >> c) & 1u) ? -INFINITY : val[c];
                    if (v > bv1)      { bv2 = bv1; bc2 = bc1; bv1 = v; bc1 = c; }
                    else if (v > bv2) { bv2 = v; bc2 = c; }
                }
                have2 = true;
            }
        }
    }
    bool availb = (lane < 16) && (myVal > -INFINITY) && (myIdx != i);
    unsigned avail = __ballot_sync(FULL, availb) & 0xFFFFu;
    int safeIdx = (lane < 16 && myVal > -INFINITY) ? myIdx : i;

#pragma unroll
    for (int t2 = 0; t2 < 10; t2++) {
        int e = lane + 32*t2;
        int a = e / 17, b = e - a*17;
        int ta = __shfl_sync(FULL, safeIdx, a & 15);
        int tb = __shfl_sync(FULL, safeIdx, b & 15);
        if (e < 289) {
            int t_a = (a >= 16) ? i : ta;
            int t_b = (b >= 16) ? i : tb;
            int row = max(t_a, t_b), col = min(t_a, t_b);
            Gm[wrp][a][b] = Gh[(size_t)row*SEQ + col];
        }
    }
    __syncwarp();

    const int cl = lane & 15;
    float Gii  = Gm[wrp][16][16];
    float detS = Gii;
    float curS = -logf(Gii + 1e-6f);
    int count = 1;
    float w[8];
    float w0 = Gm[wrp][cl][16] / sqrtf(Gii);
    w[0] = w0;
#pragma unroll
    for (int j = 1; j < 8; j++) w[j] = 0.f;
    float ec = Gm[wrp][cl][cl] - w0*w0;
    int selTok[8];
#pragma unroll
    for (int j = 0; j < 8; j++) selTok[j] = i;

    for (int step = 0; step < 7; step++) {
        bool av = (lane < 16) && ((avail >> lane) & 1u);
        float s = av ? (-logf(detS*ec + 1e-6f) / (float)(count + 1)) : -INFINITY;
        unsigned m = fmap(s);
        unsigned mmax = __reduce_max_sync(FULL, m);
        unsigned ball = __ballot_sync(FULL, m == mmax);
        int bl = __ffs(ball) - 1;
        float bs = funmap(mmax);

        bool anyAvail = (avail != 0u);
        bool accept = anyAvail && ((bs > curS) || (count < 2));
        if (!accept) break;

        float eb = __shfl_sync(FULL, ec, bl);
        float Lb = sqrtf(eb);
        float dot = 0.f;
#pragma unroll
        for (int j = 0; j < 7; j++) {
            float wbj = __shfl_sync(FULL, w[j], bl);
            if (j < count) dot += w[j]*wbj;
        }
        float wn = (Gm[wrp][cl][bl] - dot) / Lb;
#pragma unroll
        for (int j = 1; j < 8; j++) if (j == count) w[j] = wn;
        ec -= wn*wn;
        detS *= eb;
        curS = bs;
        int btok = __shfl_sync(FULL, myIdx, bl);
#pragma unroll
        for (int j = 1; j < 8; j++) if (j == count) selTok[j] = btok;
        count++;
        avail &= ~(1u << bl);
    }

    float a0 = 0.f, a1 = 0.f;
#pragma unroll
    for (int r = 0; r < 8; r++) {
        if (r < count) {
            const float* vr = vb + (size_t)selTok[r]*HS;
            a0 += vr[lane];
            a1 += vr[lane + 32];
        }
    }
    float cnt2 = (float)count;
    float o0 = a0 / cnt2, o1 = a1 / cnt2;
    int bb = bh / NHEAD, h = bh % NHEAD;
    size_t yoff = ((size_t)(bb*SEQ + i))*CDIM + h*HS;
    float h0 = tf32_rnd(o0), l0 = tf32_rnd(o0 - h0);
    float h1 = tf32_rnd(o1), l1 = tf32_rnd(o1 - h1);
    g_yh[yoff + lane]      = h0;  g_yl[yoff + lane]      = l0;
    g_yh[yoff + lane + 32] = h1;  g_yl[yoff + lane + 32] = l1;
}

// ---------------------------------------------------------------------------
extern "C" void kernel_launch(void* const* d_in, const int* in_sizes, int n_in,
                              void* d_out, int out_size)
{
    const float* x      = (const float*)d_in[0];
    const float* W_attn = (const float*)d_in[1];
    const float* b_attn = (const float*)d_in[2];
    const float* W_proj = (const float*)d_in[3];
    const float* b_proj = (const float*)d_in[4];
    float* out = (float*)d_out;

    static int smem_set = 0;
    if (!smem_set) {
        cudaFuncSetAttribute((const void*)tf32_gemm<2,3>,
                             cudaFuncAttributeMaxDynamicSharedMemorySize, GEMM_SMEM2);
        cudaFuncSetAttribute((const void*)tf32_gemm<2,1>,
                             cudaFuncAttributeMaxDynamicSharedMemorySize, GEMM_SMEM2);
        cudaFuncSetAttribute((const void*)tf32_gemm<1,2>,
                             cudaFuncAttributeMaxDynamicSharedMemorySize, GEMM_SMEM1);
        smem_set = 1;
    }

    const int ntot = NX + NWA + NWP;
    split3_kernel<<<(ntot/4 + 255)/256, 256>>>(x, W_attn, W_proj);

    {   // q/k columns (0..1535): full 3-pass precision (selection-critical)
        dim3 grid(12, (BATCH*SEQ)/128);
        tf32_gemm<2,3><<<grid, 256, GEMM_SMEM2>>>(b_attn, out, BATCH*SEQ, 3*CDIM, CDIM, 0, 0);
    }
    {   // v columns (1536..2303): 1-pass (output tolerance only)
        dim3 grid(6, (BATCH*SEQ)/128);
        tf32_gemm<2,1><<<grid, 256, GEMM_SMEM2>>>(b_attn, out, BATCH*SEQ, 3*CDIM, CDIM, 0, 12);
    }
    {   // sim + gram fused (lower-tri blocks, per head)
        dim3 grid(4, 4, 2*BH);
        sim_tf32<<<grid, 256>>>();
    }
    {   // DPP attention -> g_yh/g_yl
        dim3 grid(SEQ/DW, BH);
        dpp_kernel<<<grid, 32*DW>>>();
    }
    {   // Proj: 2-pass, 64-row tiles for full-chip spread
        dim3 grid(CDIM/128, (BATCH*SEQ)/64);
        tf32_gemm<1,2><<<grid, 256, GEMM_SMEM1>>>(b_proj, out, BATCH*SEQ, CDIM, CDIM, 1, 0);
    }
}

// round 16
// speedup vs baseline: 1.1140x; 1.0795x over previous
#include <cuda_runtime.h>
#include <cuda_bf16.h>
#include <math.h>
#include <float.h>

#define BATCH 4
#define SEQ   512
#define CDIM  768
#define NHEAD 12
#define HS    64
#define BH    (BATCH*NHEAD)      // 48
#define DW    8                  // warps (tokens) per dpp block

#define NX  (BATCH*SEQ*CDIM)     // 1572864
#define NWA (CDIM*3*CDIM)        // 1769472
#define NWP (CDIM*CDIM)          // 589824

// ---------------- device scratch (allocation forbidden) ----------------
__device__ float g_v   [BH*SEQ*HS];
__device__ float g_sim [(size_t)BH*SEQ*SEQ];   // q_i . k_j   (lower-tri blocks)
__device__ float g_gram[(size_t)BH*SEQ*SEQ];   // k_i . k_j   (lower-tri blocks)

// tf32 split operands (fp32 bit patterns)
__device__ float g_xh [NX],  g_xl [NX];
__device__ float g_Wah[NWA], g_Wal[NWA];
__device__ float g_Wph[NWP], g_Wpl[NWP];
__device__ float g_yh [NX],  g_yl [NX];         // written by dpp epilogue
__device__ float g_qh [BH*SEQ*HS], g_ql [BH*SEQ*HS];  // q splits (from qkv epi)
__device__ float g_kh [BH*SEQ*HS], g_kl [BH*SEQ*HS];  // k splits (from qkv epi)

// ---------------- helpers ----------------
__device__ __forceinline__ float tf32_rnd(float x)
{
    unsigned r;
    asm("cvt.rna.tf32.f32 %0, %1;" : "=r"(r) : "f"(x));
    return __uint_as_float(r);
}

__device__ __forceinline__ void mma_tf32(float* c, const float* a, float b0, float b1)
{
    asm volatile("mma.sync.aligned.m16n8k8.row.col.f32.tf32.tf32.f32 "
        "{%0,%1,%2,%3}, {%4,%5,%6,%7}, {%8,%9}, {%0,%1,%2,%3};"
        : "+f"(c[0]), "+f"(c[1]), "+f"(c[2]), "+f"(c[3])
        : "r"(__float_as_uint(a[0])), "r"(__float_as_uint(a[1])),
          "r"(__float_as_uint(a[2])), "r"(__float_as_uint(a[3])),
          "r"(__float_as_uint(b0)),   "r"(__float_as_uint(b1)));
}

__device__ __forceinline__ void cp16(unsigned dst, const float* src)
{
    asm volatile("cp.async.ca.shared.global [%0], [%1], 16;" :: "r"(dst), "l"(src));
}

// monotonic float<->u32 map: preserves total order, NaN maps above +inf
__device__ __forceinline__ unsigned fmap(float v)
{
    unsigned u = __float_as_uint(v);
    return (u & 0x80000000u) ? ~u : (u | 0x80000000u);
}
__device__ __forceinline__ float funmap(unsigned m)
{
    unsigned u = (m & 0x80000000u) ? (m ^ 0x80000000u) : ~m;
    return __uint_as_float(u);
}

// ---------------- fused split kernel: x, W_attn, W_proj -> tf32 hi/lo ------
__global__ __launch_bounds__(256)
void split3_kernel(const float* __restrict__ x, const float* __restrict__ wa,
                   const float* __restrict__ wp)
{
    int i = (blockIdx.x*256 + threadIdx.x) * 4;
    const float* s; float *hi, *lo; int off;
    if (i < NX)              { s = x;  hi = g_xh;  lo = g_xl;  off = i; }
    else if (i < NX+NWA)     { s = wa; hi = g_Wah; lo = g_Wal; off = i - NX; }
    else if (i < NX+NWA+NWP) { s = wp; hi = g_Wph; lo = g_Wpl; off = i - NX - NWA; }
    else return;
    float4 v = *(const float4*)(s + off);
    float4 h, l;
    h.x = tf32_rnd(v.x); l.x = tf32_rnd(v.x - h.x);
    h.y = tf32_rnd(v.y); l.y = tf32_rnd(v.y - h.y);
    h.z = tf32_rnd(v.z); l.z = tf32_rnd(v.z - h.z);
    h.w = tf32_rnd(v.w); l.w = tf32_rnd(v.w - h.w);
    *(float4*)&hi[off] = h;
    *(float4*)&lo[off] = l;
}

// ---------------- qkv scatter: q/k as tf32 splits, v fp32 ----------------
__device__ __forceinline__ void scatter_qkv(int row, int gc, float v0, float v1)
{
    int sect = gc / CDIM;              // 0=q 1=k 2=v
    int cc = gc - sect*CDIM;
    int h = cc >> 6, dd = cc & 63;
    int bb = row >> 9, t = row & 511;
    size_t off = ((size_t)(bb*NHEAD + h)*SEQ + t)*HS + dd;
    if (sect == 2) {
        *(float2*)&g_v[off] = make_float2(v0, v1);
    } else {
        float h0 = tf32_rnd(v0), l0 = tf32_rnd(v0 - h0);
        float h1 = tf32_rnd(v1), l1 = tf32_rnd(v1 - h1);
        float *hi = (sect == 0) ? g_qh : g_kh;
        float *lo = (sect == 0) ? g_ql : g_kl;
        *(float2*)&hi[off] = make_float2(h0, h1);
        *(float2*)&lo[off] = make_float2(l0, l1);
    }
}

// ---------------- 3xTF32 GEMM, cp.async 2-stage, K-chunk 16 ----------------
// MT = m-subtiles per warp (2 -> 128-row CTA, 1 -> 64-row CTA).
// PASSES (compile-time): 3 = AhBh+AhBl+AlBh, 2 = AhBh+AhBl.
template<int MT, int PASSES>
__global__ __launch_bounds__(256, 2)
void tf32_gemm(const float* __restrict__ bias, float* __restrict__ Cout,
               int M, int N, int K, int mode)
{
    constexpr int AROWS = 64*MT;
    constexpr int APART = AROWS*20;
    constexpr int BOFF  = 2*APART;
    constexpr int STGF  = BOFF + 2*2176;
    constexpr int AJ    = (PASSES >= 3) ? 2*MT : MT;
    constexpr int BJ    = (PASSES >= 2) ? 4 : 2;

    extern __shared__ __align__(16) float sm[];

    const float *Ah, *Al, *Bh, *Bl;
    if (mode == 0) { Ah = g_xh; Al = g_xl; Bh = g_Wah; Bl = g_Wal; }
    else           { Ah = g_yh; Al = g_yl; Bh = g_Wph; Bl = g_Wpl; }

    const int tid = threadIdx.x, lane = tid & 31, wid = tid >> 5;
    const int bm = blockIdx.y, bn = blockIdx.x;
    const int wm = wid & 3, wn = wid >> 2;
    const int g = lane >> 2, t = lane & 3;

    const unsigned smbase = (unsigned)__cvta_generic_to_shared(sm);

    float acc[MT][8][4];
#pragma unroll
    for (int a = 0; a < MT; a++)
#pragma unroll
        for (int b = 0; b < 8; b++)
#pragma unroll
            for (int c = 0; c < 4; c++) acc[a][b][c] = 0.f;

    const int NC = K >> 4;

    auto issue = [&](int s, int k0) {
        unsigned base = smbase + (unsigned)(s*STGF)*4u;
#pragma unroll
        for (int j = 0; j < AJ; j++) {
            int id = tid + 256*j;
            int sp = id / (256*MT), rem = id % (256*MT), row = rem >> 2, q = (rem & 3)*4;
            const float* src = (sp ? Al : Ah) + (size_t)(bm*AROWS + row)*K + k0 + q;
            cp16(base + (unsigned)(sp*APART + row*20 + q)*4u, src);
        }
#pragma unroll
        for (int j = 0; j < BJ; j++) {
            int id = tid + 256*j;
            int sp = id >> 9, rem = id & 511, kr = rem >> 5, nq = (rem & 31)*4;
            const float* src = (sp ? Bl : Bh) + (size_t)(k0 + kr)*N + bn*128 + nq;
            cp16(base + (unsigned)(BOFF + sp*2176 + kr*136 + nq)*4u, src);
        }
        asm volatile("cp.async.commit_group;");
    };

    issue(0, 0);

    for (int c = 0; c < NC; c++) {
        if (c + 1 < NC) {
            issue((c+1) & 1, (c+1)*16);
            asm volatile("cp.async.wait_group 1;");
        } else {
            asm volatile("cp.async.wait_group 0;");
        }
        __syncthreads();

        const float* S = sm + (c & 1)*STGF;

#pragma unroll
        for (int ks = 0; ks < 16; ks += 8) {
            float ah[MT][4], al[MT][4];
#pragma unroll
            for (int mt = 0; mt < MT; mt++) {
                int m0 = (wm*(16*MT) + mt*16 + g)*20 + ks + t;
                ah[mt][0] = S[m0];           ah[mt][1] = S[m0 + 160];
                ah[mt][2] = S[m0 + 4];       ah[mt][3] = S[m0 + 164];
                if (PASSES >= 3) {
                    al[mt][0] = S[APART + m0];   al[mt][1] = S[APART + m0 + 160];
                    al[mt][2] = S[APART + m0+4]; al[mt][3] = S[APART + m0 + 164];
                }
            }
            int nb0 = wn*64 + g;
            float bh0 = S[BOFF + (ks+t)*136 + nb0];
            float bh1 = S[BOFF + (ks+t+4)*136 + nb0];
            float bl0 = 0.f, bl1 = 0.f;
            if (PASSES >= 2) {
                bl0 = S[BOFF + 2176 + (ks+t)*136 + nb0];
                bl1 = S[BOFF + 2176 + (ks+t+4)*136 + nb0];
            }
#pragma unroll
            for (int nt = 0; nt < 8; nt++) {
                float cbh0 = bh0, cbh1 = bh1, cbl0 = bl0, cbl1 = bl1;
                if (nt < 7) {
                    int nb = wn*64 + (nt+1)*8 + g;
                    bh0 = S[BOFF + (ks+t)*136 + nb];
                    bh1 = S[BOFF + (ks+t+4)*136 + nb];
                    if (PASSES >= 2) {
                        bl0 = S[BOFF + 2176 + (ks+t)*136 + nb];
                        bl1 = S[BOFF + 2176 + (ks+t+4)*136 + nb];
                    }
                }
#pragma unroll
                for (int mt = 0; mt < MT; mt++) {
                    mma_tf32(acc[mt][nt], ah[mt], cbh0, cbh1);
                    if (PASSES >= 2) mma_tf32(acc[mt][nt], ah[mt], cbl0, cbl1);
                    if (PASSES >= 3) mma_tf32(acc[mt][nt], al[mt], cbh0, cbh1);
                }
            }
        }
        __syncthreads();
    }

    // epilogue
#pragma unroll
    for (int mt = 0; mt < MT; mt++) {
        int r0 = bm*AROWS + wm*(16*MT) + mt*16 + g;
#pragma unroll
        for (int nt = 0; nt < 8; nt++) {
            int gc = bn*128 + wn*64 + nt*8 + t*2;
            float b0 = bias[gc], b1 = bias[gc+1];
            float v00 = acc[mt][nt][0] + b0, v01 = acc[mt][nt][1] + b1;
            float v10 = acc[mt][nt][2] + b0, v11 = acc[mt][nt][3] + b1;
            if (mode == 1) {
                *(float2*)&Cout[(size_t)r0*N + gc]     = make_float2(v00, v01);
                *(float2*)&Cout[(size_t)(r0+8)*N + gc] = make_float2(v10, v11);
            } else {
                scatter_qkv(r0,     gc, v00, v01);
                scatter_qkv(r0 + 8, gc, v10, v11);
            }
        }
    }
}

#define STGF2 (2*2560 + 2*2176)
#define GEMM_SMEM2 (2*STGF2*4)          // MT=2 stage bytes
#define STGF1 (2*1280 + 2*2176)
#define GEMM_SMEM1 (2*STGF1*4)          // MT=1 stage bytes

// ---------------- sim+gram fused, cp.async from precomputed splits --------
// Out = A K^T per head; z < BH -> sim (A=q), else gram (A=k). Lower-tri only.
// Stage: Ah[2560] Al[2560] Bh[2560] Bl[2560] (128 rows x pitch 20, 16 k-cols)
#define SIMSTGF (4*2560)
#define SIM_SMEM (2*SIMSTGF*4)

__global__ __launch_bounds__(256, 2)
void sim_cp()
{
    const int bm = blockIdx.y, bn = blockIdx.x;
    if (bn > bm) return;
    const int z = blockIdx.z;
    const int bh = (z < BH) ? z : (z - BH);
    const int mode = (z < BH) ? 0 : 1;

    extern __shared__ __align__(16) float sm[];

    const float* __restrict__ Ah = (mode ? g_kh : g_qh) + (size_t)bh*SEQ*HS;
    const float* __restrict__ Al = (mode ? g_kl : g_ql) + (size_t)bh*SEQ*HS;
    const float* __restrict__ Bh = g_kh + (size_t)bh*SEQ*HS;
    const float* __restrict__ Bl = g_kl + (size_t)bh*SEQ*HS;

    const int tid = threadIdx.x, lane = tid & 31, wid = tid >> 5;
    const int wm = wid & 3, wn = wid >> 2;
    const int g = lane >> 2, t = lane & 3;

    const unsigned smbase = (unsigned)__cvta_generic_to_shared(sm);

    float acc[2][8][4];
#pragma unroll
    for (int a = 0; a < 2; a++)
#pragma unroll
        for (int b = 0; b < 8; b++)
#pragma unroll
            for (int c = 0; c < 4; c++) acc[a][b][c] = 0.f;

    auto issue = [&](int s, int d0) {
        unsigned base = smbase + (unsigned)(s*SIMSTGF)*4u;
        // A: 2 splits x 128 rows x 4 quads = 1024 -> 4/thread
#pragma unroll
        for (int j = 0; j < 4; j++) {
            int id = tid + 256*j;
            int sp = id >> 9, rem = id & 511, row = rem >> 2, q = (rem & 3)*4;
            const float* src = (sp ? Al : Ah) + (size_t)(bm*128 + row)*HS + d0 + q;
            cp16(base + (unsigned)(sp*2560 + row*20 + q)*4u, src);
        }
        // B: same pattern
#pragma unroll
        for (int j = 0; j < 4; j++) {
            int id = tid + 256*j;
            int sp = id >> 9, rem = id & 511, row = rem >> 2, q = (rem & 3)*4;
            const float* src = (sp ? Bl : Bh) + (size_t)(bn*128 + row)*HS + d0 + q;
            cp16(base + (unsigned)(5120 + sp*2560 + row*20 + q)*4u, src);
        }
        asm volatile("cp.async.commit_group;");
    };

    issue(0, 0);
    const int NC = HS >> 4;   // 4 chunks

    for (int c = 0; c < NC; c++) {
        if (c + 1 < NC) {
            issue((c+1) & 1, (c+1)*16);
            asm volatile("cp.async.wait_group 1;");
        } else {
            asm volatile("cp.async.wait_group 0;");
        }
        __syncthreads();

        const float* S = sm + (c & 1)*SIMSTGF;

#pragma unroll
        for (int ks = 0; ks < 16; ks += 8) {
            float ah[2][4], al[2][4];
#pragma unroll
            for (int mt = 0; mt < 2; mt++) {
                int m0 = (wm*32 + mt*16 + g)*20 + ks + t;
                ah[mt][0] = S[m0];          ah[mt][1] = S[m0 + 160];
                ah[mt][2] = S[m0 + 4];      ah[mt][3] = S[m0 + 164];
                al[mt][0] = S[2560 + m0];   al[mt][1] = S[2560 + m0 + 160];
                al[mt][2] = S[2560 + m0+4]; al[mt][3] = S[2560 + m0 + 164];
            }
#pragma unroll
            for (int nt = 0; nt < 8; nt++) {
                int n0 = 5120 + (wn*64 + nt*8 + g)*20 + ks + t;
                float bh0 = S[n0];
                float bh1 = S[n0 + 4];
                float bl0 = S[n0 + 2560];
                float bl1 = S[n0 + 2564];
#pragma unroll
                for (int mt = 0; mt < 2; mt++) {
                    mma_tf32(acc[mt][nt], ah[mt], bh0, bh1);
                    mma_tf32(acc[mt][nt], ah[mt], bl0, bl1);
                    mma_tf32(acc[mt][nt], al[mt], bh0, bh1);
                }
            }
        }
        __syncthreads();
    }

    float* Sout = (mode ? g_gram : g_sim) + (size_t)bh*SEQ*SEQ;
#pragma unroll
    for (int mt = 0; mt < 2; mt++) {
        int r0 = bm*128 + wm*32 + mt*16 + g;
#pragma unroll
        for (int nt = 0; nt < 8; nt++) {
            int gc = bn*128 + wn*64 + nt*8 + t*2;
            *(float2*)&Sout[(size_t)r0*SEQ + gc]     = make_float2(acc[mt][nt][0], acc[mt][nt][1]);
            *(float2*)&Sout[(size_t)(r0+8)*SEQ + gc] = make_float2(acc[mt][nt][2], acc[mt][nt][3]);
        }
    }
}

// ---------------- DPP: gram gathered from g_gram (proven) -----------------
__global__ __launch_bounds__(32*DW)
void dpp_kernel()
{
    __shared__ float Gm[DW][17][17];

    const unsigned FULL = 0xffffffffu;
    const int lane = threadIdx.x & 31;
    const int wrp  = threadIdx.x >> 5;
    const int i  = blockIdx.x * DW + wrp;
    const int bh = blockIdx.y;
    const int nvalid = i + 1;

    const float* __restrict__ vb = g_v + (size_t)bh*SEQ*HS;
    const float* __restrict__ simRow = g_sim + ((size_t)bh*SEQ + i)*SEQ;
    const float* __restrict__ Gh = g_gram + (size_t)bh*SEQ*SEQ;

    float val[16];
    {
        const float4* sr = (const float4*)simRow;
#pragma unroll
        for (int q = 0; q < 4; q++) {
            float4 v4 = sr[lane*4 + q];
            val[q*4+0] = v4.x; val[q*4+1] = v4.y;
            val[q*4+2] = v4.z; val[q*4+3] = v4.w;
        }
    }
    int cnt = nvalid - lane*16;
    cnt = (cnt < 0) ? 0 : (cnt > 16 ? 16 : cnt);
    unsigned dead = (0xFFFFu << cnt) & 0xFFFFu;

    float bv1 = -INFINITY, bv2 = -INFINITY; int bc1 = 0, bc2 = 0;
#pragma unroll
    for (int c = 0; c < 16; c++) {
        float v = ((dead >> c) & 1u) ? -INFINITY : val[c];
        if (v > bv1)      { bv2 = bv1; bc2 = bc1; bv1 = v; bc1 = c; }
        else if (v > bv2) { bv2 = v; bc2 = c; }
    }
    bool have2 = true;

    float myVal = -INFINITY; int myIdx = i;
    for (int t = 0; t < 16; t++) {
        unsigned m = fmap(bv1);
        unsigned mmax = __reduce_max_sync(FULL, m);
        unsigned ball = __ballot_sync(FULL, m == mmax);
        int wl = __ffs(ball) - 1;
        int wc = __shfl_sync(FULL, bc1, wl);
        if (lane == t) { myVal = funmap(mmax); myIdx = wl*16 + wc; }
        if (lane == wl) {
            dead |= 1u << bc1;
            if (have2) {
                bv1 = bv2; bc1 = bc2; have2 = false;
            } else {
                bv1 = -INFINITY; bc1 = 0; bv2 = -INFINITY; bc2 = 0;
#pragma unroll
                for (int c = 0; c < 16; c++) {
                    float v = ((dead >> c) & 1u) ? -INFINITY : val[c];
                    if (v > bv1)      { bv2 = bv1; bc2 = bc1; bv1 = v; bc1 = c; }
                    else if (v > bv2) { bv2 = v; bc2 = c; }
                }
                have2 = true;
            }
        }
    }
    bool availb = (lane < 16) && (myVal > -INFINITY) && (myIdx != i);
    unsigned avail = __ballot_sync(FULL, availb) & 0xFFFFu;
    int safeIdx = (lane < 16 && myVal > -INFINITY) ? myIdx : i;

#pragma unroll
    for (int t2 = 0; t2 < 10; t2++) {
        int e = lane + 32*t2;
        int a = e / 17, b = e - a*17;
        int ta = __shfl_sync(FULL, safeIdx, a & 15);
        int tb = __shfl_sync(FULL, safeIdx, b & 15);
        if (e < 289) {
            int t_a = (a >= 16) ? i : ta;
            int t_b = (b >= 16) ? i : tb;
            int row = max(t_a, t_b), col = min(t_a, t_b);
            Gm[wrp][a][b] = Gh[(size_t)row*SEQ + col];
        }
    }
    __syncwarp();

    const int cl = lane & 15;
    float Gii  = Gm[wrp][16][16];
    float detS = Gii;
    float curS = -logf(Gii + 1e-6f);
    int count = 1;
    float w[8];
    float w0 = Gm[wrp][cl][16] / sqrtf(Gii);
    w[0] = w0;
#pragma unroll
    for (int j = 1; j < 8; j++) w[j] = 0.f;
    float ec = Gm[wrp][cl][cl] - w0*w0;
    int selTok[8];
#pragma unroll
    for (int j = 0; j < 8; j++) selTok[j] = i;

    for (int step = 0; step < 7; step++) {
        bool av = (lane < 16) && ((avail >> lane) & 1u);
        float s = av ? (-logf(detS*ec + 1e-6f) / (float)(count + 1)) : -INFINITY;
        unsigned m = fmap(s);
        unsigned mmax = __reduce_max_sync(FULL, m);
        unsigned ball = __ballot_sync(FULL, m == mmax);
        int bl = __ffs(ball) - 1;
        float bs = funmap(mmax);

        bool anyAvail = (avail != 0u);
        bool accept = anyAvail && ((bs > curS) || (count < 2));
        if (!accept) break;

        float eb = __shfl_sync(FULL, ec, bl);
        float Lb = sqrtf(eb);
        float dot = 0.f;
#pragma unroll
        for (int j = 0; j < 7; j++) {
            float wbj = __shfl_sync(FULL, w[j], bl);
            if (j < count) dot += w[j]*wbj;
        }
        float wn = (Gm[wrp][cl][bl] - dot) / Lb;
#pragma unroll
        for (int j = 1; j < 8; j++) if (j == count) w[j] = wn;
        ec -= wn*wn;
        detS *= eb;
        curS = bs;
        int btok = __shfl_sync(FULL, myIdx, bl);
#pragma unroll
        for (int j = 1; j < 8; j++) if (j == count) selTok[j] = btok;
        count++;
        avail &= ~(1u << bl);
    }

    float a0 = 0.f, a1 = 0.f;
#pragma unroll
    for (int r = 0; r < 8; r++) {
        if (r < count) {
            const float* vr = vb + (size_t)selTok[r]*HS;
            a0 += vr[lane];
            a1 += vr[lane + 32];
        }
    }
    float cnt2 = (float)count;
    float o0 = a0 / cnt2, o1 = a1 / cnt2;
    int bb = bh / NHEAD, h = bh % NHEAD;
    size_t yoff = ((size_t)(bb*SEQ + i))*CDIM + h*HS;
    float h0 = tf32_rnd(o0), l0 = tf32_rnd(o0 - h0);
    float h1 = tf32_rnd(o1), l1 = tf32_rnd(o1 - h1);
    g_yh[yoff + lane]      = h0;  g_yl[yoff + lane]      = l0;
    g_yh[yoff + lane + 32] = h1;  g_yl[yoff + lane + 32] = l1;
}

// ---------------------------------------------------------------------------
extern "C" void kernel_launch(void* const* d_in, const int* in_sizes, int n_in,
                              void* d_out, int out_size)
{
    const float* x      = (const float*)d_in[0];
    const float* W_attn = (const float*)d_in[1];
    const float* b_attn = (const float*)d_in[2];
    const float* W_proj = (const float*)d_in[3];
    const float* b_proj = (const float*)d_in[4];
    float* out = (float*)d_out;

    static int smem_set = 0;
    if (!smem_set) {
        cudaFuncSetAttribute((const void*)tf32_gemm<2,3>,
                             cudaFuncAttributeMaxDynamicSharedMemorySize, GEMM_SMEM2);
        cudaFuncSetAttribute((const void*)tf32_gemm<1,2>,
                             cudaFuncAttributeMaxDynamicSharedMemorySize, GEMM_SMEM1);
        cudaFuncSetAttribute((const void*)sim_cp,
                             cudaFuncAttributeMaxDynamicSharedMemorySize, SIM_SMEM);
        smem_set = 1;
    }

    const int ntot = NX + NWA + NWP;
    split3_kernel<<<(ntot/4 + 255)/256, 256>>>(x, W_attn, W_proj);

    {   // QKV: single 3-pass launch (proven fastest); epilogue splits q/k
        dim3 grid(3*CDIM/128, (BATCH*SEQ)/128);
        tf32_gemm<2,3><<<grid, 256, GEMM_SMEM2>>>(b_attn, out, BATCH*SEQ, 3*CDIM, CDIM, 0);
    }
    {   // sim + gram fused, cp.async from precomputed splits
        dim3 grid(4, 4, 2*BH);
        sim_cp<<<grid, 256, SIM_SMEM>>>();
    }
    {   // DPP attention -> g_yh/g_yl
        dim3 grid(SEQ/DW, BH);
        dpp_kernel<<<grid, 32*DW>>>();
    }
    {   // Proj: 2-pass, 64-row tiles for full-chip spread
        dim3 grid(CDIM/128, (BATCH*SEQ)/64);
        tf32_gemm<1,2><<<grid, 256, GEMM_SMEM1>>>(b_proj, out, BATCH*SEQ, CDIM, CDIM, 1);
    }
}